// round 2
// baseline (speedup 1.0000x reference)
#include <cuda_runtime.h>

// PatchEmbed: gather KNN -> center-subtract -> MLP(3->64->128->256, relu, relu, none) -> max over K
// Shapes: xyz (8,16384,3) f32 | centers (8,2048,3) f32 | idx (8,2048,32) i32
//         W1 (64,3) b1(64) | W2 (128,64) b2(128) | W3 (256,128) b3(256)
// out (8,2048,256) f32
//
// Strategy: one CTA per (b,m). 256 threads. All heavy math uses packed
// fma.rn.f32x2 (2 fp32 FMAs per issue slot -> 2x the scalar FFMA rate on sm_103a).

constexpr int Bb   = 8;
constexpr int Nn   = 16384;
constexpr int Mc   = 2048;
constexpr int Kn   = 32;
constexpr int C1   = 64;
constexpr int C2   = 128;
constexpr int C3   = 256;

__device__ __forceinline__ unsigned long long pfma2(unsigned long long a,
                                                    unsigned long long b,
                                                    unsigned long long c) {
    unsigned long long d;
    asm("fma.rn.f32x2 %0, %1, %2, %3;" : "=l"(d) : "l"(a), "l"(b), "l"(c));
    return d;
}

__device__ __forceinline__ float2 u2f2(unsigned long long u) {
    float2 f;
    asm("mov.b64 {%0, %1}, %2;" : "=f"(f.x), "=f"(f.y) : "l"(u));
    return f;
}

__global__ __launch_bounds__(256, 1)
void patch_embed_kernel(const float* __restrict__ xyz,
                        const float* __restrict__ centers,
                        const int*   __restrict__ idx,
                        const float* __restrict__ W1, const float* __restrict__ b1,
                        const float* __restrict__ W2, const float* __restrict__ b2,
                        const float* __restrict__ W3, const float* __restrict__ b3,
                        float* __restrict__ out) {
    __shared__ float ls[Kn][3];        // local coords (center-subtracted)
    __shared__ float h1s[Kn][C1];      // 8 KB
    __shared__ float h2s[Kn][C2];      // 16 KB

    const int bm  = blockIdx.x;        // 0 .. B*Mc-1
    const int b   = bm >> 11;          // / 2048
    const int tid = threadIdx.x;

    // ---- gather neighbors + center subtract (32 threads) ----
    if (tid < Kn) {
        const int   id = idx[(size_t)bm * Kn + tid];
        const float* p = xyz + ((size_t)b * Nn + id) * 3;
        const float* c = centers + (size_t)bm * 3;
        ls[tid][0] = p[0] - c[0];
        ls[tid][1] = p[1] - c[1];
        ls[tid][2] = p[2] - c[2];
    }
    __syncthreads();

    // ---- layer 1: h1[k][c] = relu(W1[c] . local[k] + b1[c])  (2048 outputs, 8/thread)
#pragma unroll
    for (int r = 0; r < 8; r++) {
        const int o = tid + r * 256;
        const int k = o >> 6;
        const int c = o & (C1 - 1);
        const float lx = ls[k][0], ly = ls[k][1], lz = ls[k][2];
        float v = fmaf(__ldg(&W1[c * 3 + 0]), lx,
                  fmaf(__ldg(&W1[c * 3 + 1]), ly,
                  fmaf(__ldg(&W1[c * 3 + 2]), lz, __ldg(&b1[c]))));
        h1s[k][c] = fmaxf(v, 0.0f);
    }
    __syncthreads();

    // ---- layer 2: h2[k][c2] = relu(W2[c2] . h1[k] + b2[c2])
    // thread -> (c2 = tid&127, kgroup = tid>>7 handling 16 ks). W2 row in regs.
    {
        const int c2 = tid & (C2 - 1);
        const int kg = tid >> 7;                       // 0 or 1
        ulonglong2 w2r[16];                            // 64 floats
        const ulonglong2* w2g = reinterpret_cast<const ulonglong2*>(W2 + (size_t)c2 * C1);
#pragma unroll
        for (int i = 0; i < 16; i++) w2r[i] = w2g[i];
        const float bias2 = __ldg(&b2[c2]);

#pragma unroll 1
        for (int kk = 0; kk < 16; kk++) {
            const int k = kg * 16 + kk;
            const ulonglong2* h1p = reinterpret_cast<const ulonglong2*>(&h1s[k][0]);
            unsigned long long acc0 = 0ull, acc1 = 0ull;
#pragma unroll
            for (int i = 0; i < 16; i++) {
                const ulonglong2 h = h1p[i];           // LDS.128, broadcast in warp
                acc0 = pfma2(h.x, w2r[i].x, acc0);
                acc1 = pfma2(h.y, w2r[i].y, acc1);
            }
            const float2 a = u2f2(acc0), d = u2f2(acc1);
            const float s = (a.x + a.y) + (d.x + d.y) + bias2;
            h2s[k][c2] = fmaxf(s, 0.0f);
        }
    }
    __syncthreads();

    // ---- layer 3 + max over k: out[bm][c3] = max_k (W3[c3] . h2[k] + b3[c3])
    // thread = channel c3 = tid. W3 row (128 floats = 32 ull2) in registers.
    {
        ulonglong2 w3r[32];
        const ulonglong2* w3g = reinterpret_cast<const ulonglong2*>(W3 + (size_t)tid * C2);
#pragma unroll
        for (int i = 0; i < 32; i++) w3r[i] = w3g[i];
        const float bias3 = __ldg(&b3[tid]);

        float vmax = __int_as_float(0xff800000);       // -inf

#pragma unroll 1
        for (int k = 0; k < Kn; k++) {
            const ulonglong2* h2p = reinterpret_cast<const ulonglong2*>(&h2s[k][0]);
            unsigned long long acc0 = 0ull, acc1 = 0ull, acc2 = 0ull, acc3 = 0ull;
#pragma unroll
            for (int i = 0; i < 32; i += 2) {
                const ulonglong2 ha = h2p[i];          // LDS.128, broadcast
                const ulonglong2 hb = h2p[i + 1];
                acc0 = pfma2(ha.x, w3r[i].x,     acc0);
                acc1 = pfma2(ha.y, w3r[i].y,     acc1);
                acc2 = pfma2(hb.x, w3r[i + 1].x, acc2);
                acc3 = pfma2(hb.y, w3r[i + 1].y, acc3);
            }
            const float2 f0 = u2f2(acc0), f1 = u2f2(acc1);
            const float2 f2 = u2f2(acc2), f3 = u2f2(acc3);
            const float s = ((f0.x + f0.y) + (f1.x + f1.y)) +
                            ((f2.x + f2.y) + (f3.x + f3.y)) + bias3;
            vmax = fmaxf(vmax, s);
        }
        out[(size_t)bm * C3 + tid] = vmax;
    }
}

extern "C" void kernel_launch(void* const* d_in, const int* in_sizes, int n_in,
                              void* d_out, int out_size) {
    (void)in_sizes; (void)n_in; (void)out_size;
    const float* xyz     = (const float*)d_in[0];
    const float* centers = (const float*)d_in[1];
    const int*   idx     = (const int*)  d_in[2];
    const float* W1      = (const float*)d_in[3];
    const float* b1      = (const float*)d_in[4];
    const float* W2      = (const float*)d_in[5];
    const float* b2      = (const float*)d_in[6];
    const float* W3      = (const float*)d_in[7];
    const float* b3      = (const float*)d_in[8];
    float*       out     = (float*)d_out;

    dim3 grid(Bb * Mc);   // 16384 CTAs, one per (b, m)
    dim3 block(256);
    patch_embed_kernel<<<grid, block>>>(xyz, centers, idx,
                                        W1, b1, W2, b2, W3, b3, out);
}